// round 13
// baseline (speedup 1.0000x reference)
#include <cuda_runtime.h>
#include <cuda_fp16.h>
#include <cstdint>

#define FIN   64
#define FOUT  64
#define FH    128
#define LATD  512
#define NB    16
#define HW    16384
#define KTOT  53760
#define WS    53248   // fp16 elements of packed weights per sample (single-term)

// per-sample fp16 element offsets of fragment-ordered weight buffers
#define WIN_O   0        // O=128 I=64  (8192 ele)
#define WMIDA_O 8192     // O=128 I=128 (16384)
#define WMIDB_O 24576    // O=128 I=128 (16384)
#define WOUT_O  40960    // O=64 I=128  (8192)
#define WSH_O   49152    // O=64 I=64   (4096)

__device__ __align__(16) __half g_wh[NB * WS];
__device__ __align__(16) float g_bias[NB * 512];

// ---------------- helpers ----------------
__device__ __forceinline__ uint32_t pack_f16x2(float f0, float f1) {
    uint32_t r;
    asm("cvt.rn.f16x2.f32 %0, %1, %2;" : "=r"(r) : "f"(f1), "f"(f0));
    return r;
}
__device__ __forceinline__ void split2(float f0, float f1, uint32_t& hi, uint32_t& lo) {
    asm("cvt.rn.f16x2.f32 %0, %1, %2;" : "=r"(hi) : "f"(f1), "f"(f0));
    __half2 h = *(__half2*)&hi;
    float r0 = f0 - __low2float(h), r1 = f1 - __high2float(h);
    asm("cvt.rn.f16x2.f32 %0, %1, %2;" : "=r"(lo) : "f"(r1), "f"(r0));
}

__device__ __forceinline__ void mma16816(float d[4],
    const uint32_t a[4], uint32_t b0, uint32_t b1)
{
    asm volatile(
        "mma.sync.aligned.m16n8k16.row.col.f32.f16.f16.f32 "
        "{%0,%1,%2,%3}, {%4,%5,%6,%7}, {%8,%9}, {%0,%1,%2,%3};"
        : "+f"(d[0]), "+f"(d[1]), "+f"(d[2]), "+f"(d[3])
        : "r"(a[0]), "r"(a[1]), "r"(a[2]), "r"(a[3]), "r"(b0), "r"(b1));
}

// map hypernet row k -> fragment element index / bias flag / scale
__device__ __forceinline__ int map_fel(int k, float& scale, bool& isBias) {
    const float RS128 = 0.08838834764831845f;
    const float RS64  = 0.125f;
    int o, i, I, base;
    isBias = false;
    if (k < 8192)       { o = k >> 6;            i = k & 63;  I = 64;  base = WIN_O;   scale = RS128; }
    else if (k < 24576) { int x = k - 8192;  o = x >> 7; i = x & 127; I = 128; base = WMIDA_O; scale = RS128; }
    else if (k < 40960) { int x = k - 24576; o = x >> 7; i = x & 127; I = 128; base = WMIDB_O; scale = RS128; }
    else if (k < 49152) { int x = k - 40960; o = x >> 7; i = x & 127; I = 128; base = WOUT_O;  scale = RS64; }
    else if (k < 53248) { int x = k - 49152; o = x >> 6; i = x & 63;  I = 64;  base = WSH_O;   scale = RS64; }
    else { isBias = true; scale = 1.f; return 0; }
    int KT = I / 16;
    int nt = o >> 3, kt = i >> 4;
    int tl = (o & 7) * 4 + ((i & 7) >> 1);
    int el = (((i >> 3) & 1) << 1) | (i & 1);
    return base + ((nt * KT + kt) * 32 + tl) * 4 + el;
}

// ============================================================
// Kernel A (frozen from R12): hypernetwork GEMM on tensor cores.
// 140 CTAs x 192 thr = 840 warps; depth-2 k-chunk register prefetch.
// ============================================================
__global__ __launch_bounds__(192) void hyper_kernel(
    const float* __restrict__ lat,
    const float* __restrict__ Wm,
    const float* __restrict__ bias)
{
    __shared__ __align__(16) uint4 sAhi[32][32];
    __shared__ __align__(16) uint4 sAlo[32][32];

    const int tid = threadIdx.x;
    for (int idx = tid; idx < 1024; idx += 192) {
        int kc = idx >> 5, ln = idx & 31;
        int r = ln >> 2, c = kc * 16 + (ln & 3) * 2;
        uint32_t h[4], l[4];
        split2(lat[r * 512 + c],           lat[r * 512 + c + 1],           h[0], l[0]);
        split2(lat[(r + 8) * 512 + c],     lat[(r + 8) * 512 + c + 1],     h[1], l[1]);
        split2(lat[r * 512 + c + 8],       lat[r * 512 + c + 9],           h[2], l[2]);
        split2(lat[(r + 8) * 512 + c + 8], lat[(r + 8) * 512 + c + 9],     h[3], l[3]);
        sAhi[kc][ln] = make_uint4(h[0], h[1], h[2], h[3]);
        sAlo[kc][ln] = make_uint4(l[0], l[1], l[2], l[3]);
    }
    __syncthreads();

    const int lane = tid & 31;
    const int g = blockIdx.x * 6 + (tid >> 5);   // 0..839
    const int kbase = g * 64;

    float acc[8][4];
#pragma unroll
    for (int t = 0; t < 8; t++) {
        acc[t][0] = 0.f; acc[t][1] = 0.f; acc[t][2] = 0.f; acc[t][3] = 0.f;
    }

    const int rrow = lane >> 2;
    const int cof  = (lane & 3) * 2;
    const float* __restrict__ wb = Wm + (size_t)(kbase + rrow) * LATD + cof;

    float2 buf0[16], buf1[16], buf2[16], buf3[16];

#define HPF(NB_, KC_) do {                                         \
        const float* _wn = wb + (KC_) * 16;                        \
        _Pragma("unroll")                                          \
        for (int t = 0; t < 8; t++) {                              \
            NB_[t * 2]     = *(const float2*)(_wn + t * 4096);     \
            NB_[t * 2 + 1] = *(const float2*)(_wn + t * 4096 + 8); \
        }                                                          \
    } while (0)

#define HCONS(CB_, KC_) do {                                       \
        uint4 ah4 = sAhi[KC_][lane];                               \
        uint4 al4 = sAlo[KC_][lane];                               \
        uint32_t Ah[4] = {ah4.x, ah4.y, ah4.z, ah4.w};             \
        uint32_t Al[4] = {al4.x, al4.y, al4.z, al4.w};             \
        _Pragma("unroll")                                          \
        for (int t = 0; t < 8; t++) {                              \
            uint32_t bh0, bl0, bh1, bl1;                           \
            split2(CB_[t * 2].x,     CB_[t * 2].y,     bh0, bl0);  \
            split2(CB_[t * 2 + 1].x, CB_[t * 2 + 1].y, bh1, bl1);  \
            mma16816(acc[t], Ah, bh0, bh1);                        \
            mma16816(acc[t], Al, bh0, bh1);                        \
            mma16816(acc[t], Ah, bl0, bl1);                        \
        }                                                          \
    } while (0)

    HPF(buf0, 0);
    HPF(buf1, 1);
#pragma unroll 1
    for (int kq = 0; kq < 32; kq += 4) {
        bool more = kq < 28;
        HPF(buf2, kq + 2);
        HCONS(buf0, kq);
        HPF(buf3, kq + 3);
        HCONS(buf1, kq + 1);
        if (more) HPF(buf0, kq + 4);
        HCONS(buf2, kq + 2);
        if (more) HPF(buf1, kq + 5);
        HCONS(buf3, kq + 3);
    }
#undef HPF
#undef HCONS

    // epilogue: bias + scale + fp16 pack + fragment scatter
    const int s0 = lane >> 2;           // sample rows s0, s0+8
#pragma unroll
    for (int t = 0; t < 8; t++) {
#pragma unroll
        for (int j = 0; j < 2; j++) {
            int k = kbase + t * 8 + (lane & 3) * 2 + j;
            float bk = bias[k];
            float scale; bool isBias;
            int fel = map_fel(k, scale, isBias);
            float v0 = acc[t][j]     + bk;   // sample s0
            float v1 = acc[t][j + 2] + bk;   // sample s0+8
            if (isBias) {
                g_bias[s0 * 512 + (k - 53248)]       = v0;
                g_bias[(s0 + 8) * 512 + (k - 53248)] = v1;
            } else {
                g_wh[(size_t)s0 * WS + fel]       = __float2half_rn(v0 * scale);
                g_wh[(size_t)(s0 + 8) * WS + fel] = __float2half_rn(v1 * scale);
            }
        }
    }
}

// ============================================================
// Kernel B: mma.sync fused block, M=16 per warp, 512 threads
// (16 warps = 4/SMSP for latency hiding), fp16 single-term weights,
// 2-nt transient accumulators, per-sample grid.
// ============================================================
template <int KT>
__device__ __forceinline__ void layer_fused16(
    const uint32_t (*A)[4], uint32_t (*N)[4],
    const char* __restrict__ sm, int bOff,
    const float* __restrict__ bsm, int lane, int tig)
{
#pragma unroll
    for (int c = 0; c < 8; c++) {        // chunk = 2 nt = 16 channels
        float D[2][4];
#pragma unroll
        for (int j = 0; j < 2; j++) {
            int nt = c * 2 + j;
            float b0 = bsm[nt * 8 + tig * 2];
            float b1 = bsm[nt * 8 + tig * 2 + 1];
            D[j][0] = b0; D[j][1] = b1; D[j][2] = b0; D[j][3] = b1;
        }
#pragma unroll
        for (int kt = 0; kt < KT; kt++) {
            uint2 bf[2];
#pragma unroll
            for (int j = 0; j < 2; j++) {
                int fo = (((c * 2 + j) * KT + kt) * 32 + lane) * 8;
                bf[j] = *(const uint2*)(sm + bOff + fo);
            }
#pragma unroll
            for (int j = 0; j < 2; j++)
                mma16816(D[j], A[kt], bf[j].x, bf[j].y);
        }
        // relu + fp16 pack -> next-layer A fragments (kt' = c)
        N[c][0] = pack_f16x2(fmaxf(D[0][0], 0.f), fmaxf(D[0][1], 0.f));
        N[c][1] = pack_f16x2(fmaxf(D[0][2], 0.f), fmaxf(D[0][3], 0.f));
        N[c][2] = pack_f16x2(fmaxf(D[1][0], 0.f), fmaxf(D[1][1], 0.f));
        N[c][3] = pack_f16x2(fmaxf(D[1][2], 0.f), fmaxf(D[1][3], 0.f));
    }
}

__global__ __launch_bounds__(512, 1) void conv_kernel(
    const float* __restrict__ x, float* __restrict__ out)
{
    extern __shared__ __align__(16) char smem[];
    const float* bsm = (const float*)(smem + WS * 2);

    const int tid = threadIdx.x;
    const int w = tid >> 5, lane = tid & 31;
    const int gid = lane >> 2, tig = lane & 3;
    const int b  = blockIdx.x / 9;
    const int cs = blockIdx.x % 9;

    // stage all fragment-ordered weights (106496 B) + biases (2 KB)
    {
        const uint4* src = (const uint4*)(g_wh + (size_t)b * WS);
        uint4* dst = (uint4*)smem;
        for (int i = tid; i < WS / 8; i += 512) dst[i] = src[i];
        const float4* bsrc = (const float4*)(g_bias + b * 512);
        float4* bdst = (float4*)(smem + WS * 2);
        if (tid < 128) bdst[tid] = bsrc[tid];
    }
    __syncthreads();

    const float* xb = x + (size_t)b * FIN * HW;
    float* ob = out + (size_t)b * FOUT * HW;

    uint32_t X[4][4];
    uint32_t Abuf[2][8][4];   // ping-pong [pp][kt][4]

    for (int t = cs; t < 64; t += 9) {
        const int px_lo = t * 256 + w * 16 + gid;
        const int px_hi = px_lo + 8;

        // ---- load x as fp16 A fragments ----
#pragma unroll
        for (int kt = 0; kt < 4; kt++) {
            const float* xp = xb + (size_t)(kt * 16 + tig * 2) * HW;
            X[kt][0] = pack_f16x2(xp[px_lo],          xp[HW + px_lo]);
            X[kt][1] = pack_f16x2(xp[px_hi],          xp[HW + px_hi]);
            X[kt][2] = pack_f16x2(xp[8 * HW + px_lo], xp[9 * HW + px_lo]);
            X[kt][3] = pack_f16x2(xp[8 * HW + px_hi], xp[9 * HW + px_hi]);
        }

        layer_fused16<4>(X,       Abuf[0], smem, WIN_O * 2,   bsm + 0,   lane, tig);
        layer_fused16<8>(Abuf[0], Abuf[1], smem, WMIDA_O * 2, bsm + 128, lane, tig);
        layer_fused16<8>(Abuf[1], Abuf[0], smem, WMIDB_O * 2, bsm + 256, lane, tig);

        // ---- out layer: Wout @ h + Wshort @ x, 64 ch, store ----
#pragma unroll
        for (int c = 0; c < 4; c++) {
            float D[2][4];
#pragma unroll
            for (int j = 0; j < 2; j++) {
                int ch = (c * 2 + j) * 8 + tig * 2;
                float b0 = bsm[384 + ch]     + bsm[448 + ch];
                float b1 = bsm[384 + ch + 1] + bsm[448 + ch + 1];
                D[j][0] = b0; D[j][1] = b1; D[j][2] = b0; D[j][3] = b1;
            }
#pragma unroll
            for (int kt = 0; kt < 8; kt++) {
                uint2 bf[2];
#pragma unroll
                for (int j = 0; j < 2; j++) {
                    int fo = (((c * 2 + j) * 8 + kt) * 32 + lane) * 8;
                    bf[j] = *(const uint2*)(smem + WOUT_O * 2 + fo);
                }
#pragma unroll
                for (int j = 0; j < 2; j++)
                    mma16816(D[j], Abuf[0][kt], bf[j].x, bf[j].y);
            }
#pragma unroll
            for (int kt = 0; kt < 4; kt++) {
                uint2 bf[2];
#pragma unroll
                for (int j = 0; j < 2; j++) {
                    int fo = (((c * 2 + j) * 4 + kt) * 32 + lane) * 8;
                    bf[j] = *(const uint2*)(smem + WSH_O * 2 + fo);
                }
#pragma unroll
                for (int j = 0; j < 2; j++)
                    mma16816(D[j], X[kt], bf[j].x, bf[j].y);
            }
            // store 16 channels x 16 pixels
#pragma unroll
            for (int j = 0; j < 2; j++) {
                int ch = (c * 2 + j) * 8 + tig * 2;
                float* op = ob + (size_t)ch * HW;
                op[px_lo]      = D[j][0];
                op[HW + px_lo] = D[j][1];
                op[px_hi]      = D[j][2];
                op[HW + px_hi] = D[j][3];
            }
        }
    }
}

// ============================================================
extern "C" void kernel_launch(void* const* d_in, const int* in_sizes, int n_in,
                              void* d_out, int out_size)
{
    (void)in_sizes; (void)n_in; (void)out_size;
    const float* x    = (const float*)d_in[0];
    const float* lat  = (const float*)d_in[1];
    const float* W    = (const float*)d_in[2];
    const float* bias = (const float*)d_in[3];
    float* out = (float*)d_out;

    hyper_kernel<<<140, 192>>>(lat, W, bias);

    cudaFuncSetAttribute(conv_kernel,
                         cudaFuncAttributeMaxDynamicSharedMemorySize, 110592);
    conv_kernel<<<16 * 9, 512, 110592>>>(x, out);
}

// round 14
// speedup vs baseline: 1.0974x; 1.0974x over previous
#include <cuda_runtime.h>
#include <cuda_fp16.h>
#include <cstdint>

#define FIN   64
#define FOUT  64
#define FH    128
#define LATD  512
#define NB    16
#define HW    16384
#define KTOT  53760
#define WS    53248   // fp16 elements of packed weights per sample (single-term)

// per-sample fp16 element offsets of fragment-ordered weight buffers
#define WIN_O   0        // O=128 I=64  (8192 ele)
#define WMIDA_O 8192     // O=128 I=128 (16384)
#define WMIDB_O 24576    // O=128 I=128 (16384)
#define WOUT_O  40960    // O=64 I=128  (8192)
#define WSH_O   49152    // O=64 I=64   (4096)

__device__ __align__(16) __half g_wh[NB * WS];
__device__ __align__(16) float g_bias[NB * 512];

// ---------------- helpers ----------------
__device__ __forceinline__ uint32_t pack_f16x2(float f0, float f1) {
    uint32_t r;
    asm("cvt.rn.f16x2.f32 %0, %1, %2;" : "=r"(r) : "f"(f1), "f"(f0));
    return r;
}
__device__ __forceinline__ void split2(float f0, float f1, uint32_t& hi, uint32_t& lo) {
    asm("cvt.rn.f16x2.f32 %0, %1, %2;" : "=r"(hi) : "f"(f1), "f"(f0));
    __half2 h = *(__half2*)&hi;
    float r0 = f0 - __low2float(h), r1 = f1 - __high2float(h);
    asm("cvt.rn.f16x2.f32 %0, %1, %2;" : "=r"(lo) : "f"(r1), "f"(r0));
}
__device__ __forceinline__ uint32_t smem_u32(const void* p) {
    uint32_t a;
    asm("{ .reg .u64 t; cvta.to.shared.u64 t, %1; cvt.u32.u64 %0, t; }" : "=r"(a) : "l"(p));
    return a;
}

__device__ __forceinline__ void mma16816(float d[4],
    const uint32_t a[4], uint32_t b0, uint32_t b1)
{
    asm volatile(
        "mma.sync.aligned.m16n8k16.row.col.f32.f16.f16.f32 "
        "{%0,%1,%2,%3}, {%4,%5,%6,%7}, {%8,%9}, {%0,%1,%2,%3};"
        : "+f"(d[0]), "+f"(d[1]), "+f"(d[2]), "+f"(d[3])
        : "r"(a[0]), "r"(a[1]), "r"(a[2]), "r"(a[3]), "r"(b0), "r"(b1));
}

#define CP_ASYNC16(dst, src) \
    asm volatile("cp.async.cg.shared.global [%0], [%1], 16;" :: "r"(dst), "l"(src) : "memory")
#define CP_COMMIT() asm volatile("cp.async.commit_group;" ::: "memory")
#define CP_WAIT(n)  asm volatile("cp.async.wait_group %0;" :: "n"(n) : "memory")

// map hypernet row k -> fragment element index / bias flag / scale
__device__ __forceinline__ int map_fel(int k, float& scale, bool& isBias) {
    const float RS128 = 0.08838834764831845f;
    const float RS64  = 0.125f;
    int o, i, I, base;
    isBias = false;
    if (k < 8192)       { o = k >> 6;            i = k & 63;  I = 64;  base = WIN_O;   scale = RS128; }
    else if (k < 24576) { int x = k - 8192;  o = x >> 7; i = x & 127; I = 128; base = WMIDA_O; scale = RS128; }
    else if (k < 40960) { int x = k - 24576; o = x >> 7; i = x & 127; I = 128; base = WMIDB_O; scale = RS128; }
    else if (k < 49152) { int x = k - 40960; o = x >> 7; i = x & 127; I = 128; base = WOUT_O;  scale = RS64; }
    else if (k < 53248) { int x = k - 49152; o = x >> 6; i = x & 63;  I = 64;  base = WSH_O;   scale = RS64; }
    else { isBias = true; scale = 1.f; return 0; }
    int KT = I / 16;
    int nt = o >> 3, kt = i >> 4;
    int tl = (o & 7) * 4 + ((i & 7) >> 1);
    int el = (((i >> 3) & 1) << 1) | (i & 1);
    return base + ((nt * KT + kt) * 32 + tl) * 4 + el;
}

// ============================================================
// Kernel A: hypernetwork GEMM on tensor cores, cp.async-staged W.
// 148 CTAs x 192 thr (guard g<840). Per warp: 64 rows, K=512.
// W staged coalesced (128B lines) into per-warp double-buffered
// smem (row pad 160B, bank-conflict-free fragment LDS).
// ============================================================
__global__ __launch_bounds__(192) void hyper_kernel(
    const float* __restrict__ lat,
    const float* __restrict__ Wm,
    const float* __restrict__ bias)
{
    extern __shared__ __align__(16) char hsm[];
    uint4* sAhi = (uint4*)hsm;               // [32][32] = 16 KB
    uint4* sAlo = (uint4*)(hsm + 16384);     // 16 KB
    // W stage: 6 warps x 2 stages x 64 rows x 160 B = 122880 B at +32768

    const int tid  = threadIdx.x;
    const int lane = tid & 31;
    const int w    = tid >> 5;

    // stage lat fragments hi/lo (all 32 k-chunks)
    for (int idx = tid; idx < 1024; idx += 192) {
        int kc = idx >> 5, ln = idx & 31;
        int r = ln >> 2, c = kc * 16 + (ln & 3) * 2;
        uint32_t h[4], l[4];
        split2(lat[r * 512 + c],           lat[r * 512 + c + 1],           h[0], l[0]);
        split2(lat[(r + 8) * 512 + c],     lat[(r + 8) * 512 + c + 1],     h[1], l[1]);
        split2(lat[r * 512 + c + 8],       lat[r * 512 + c + 9],           h[2], l[2]);
        split2(lat[(r + 8) * 512 + c + 8], lat[(r + 8) * 512 + c + 9],     h[3], l[3]);
        sAhi[kc * 32 + ln] = make_uint4(h[0], h[1], h[2], h[3]);
        sAlo[kc * 32 + ln] = make_uint4(l[0], l[1], l[2], l[3]);
    }
    __syncthreads();

    const int g = blockIdx.x * 6 + w;
    if (g >= 840) return;
    const int kbase = g * 64;
    const float* __restrict__ wrow = Wm + (size_t)kbase * 512;

    const uint32_t wbase_off = 32768 + w * 20480;      // byte offset in hsm
    const uint32_t wsm_hw    = smem_u32(hsm) + wbase_off;

    float acc[8][4];
#pragma unroll
    for (int t = 0; t < 8; t++) {
        acc[t][0] = 0.f; acc[t][1] = 0.f; acc[t][2] = 0.f; acc[t][3] = 0.f;
    }

    const int rrow = lane >> 2;
    const int tig  = lane & 3;

    // stage: 64 rows x 128 B (2 k-chunks) coalesced; 4 rows per instr
#define HSTAGE(DSTHW, KC2) do {                                              \
        const float* _s = wrow + (size_t)(lane >> 3) * 512                   \
                          + (KC2) * 32 + (lane & 7) * 4;                     \
        uint32_t _d = (DSTHW) + (lane >> 3) * 160 + (lane & 7) * 16;         \
        _Pragma("unroll")                                                    \
        for (int i = 0; i < 16; i++)                                         \
            CP_ASYNC16(_d + i * 4 * 160, _s + (size_t)i * 4 * 512);          \
    } while (0)

    // consume one k-chunk from staged smem
#define HCONS(COFF, KC) do {                                                 \
        uint4 ah4 = sAhi[(KC) * 32 + lane];                                  \
        uint4 al4 = sAlo[(KC) * 32 + lane];                                  \
        uint32_t Ah[4] = {ah4.x, ah4.y, ah4.z, ah4.w};                       \
        uint32_t Al[4] = {al4.x, al4.y, al4.z, al4.w};                       \
        const char* _c = hsm + (COFF) + ((KC) & 1) * 64 + rrow * 160 + tig * 8; \
        _Pragma("unroll")                                                    \
        for (int t = 0; t < 8; t++) {                                        \
            float2 w0 = *(const float2*)(_c + t * 8 * 160);                  \
            float2 w1 = *(const float2*)(_c + t * 8 * 160 + 32);             \
            uint32_t bh0, bl0, bh1, bl1;                                     \
            split2(w0.x, w0.y, bh0, bl0);                                    \
            split2(w1.x, w1.y, bh1, bl1);                                    \
            mma16816(acc[t], Ah, bh0, bh1);                                  \
            mma16816(acc[t], Al, bh0, bh1);                                  \
            mma16816(acc[t], Ah, bl0, bl1);                                  \
        }                                                                    \
    } while (0)

    HSTAGE(wsm_hw, 0);         CP_COMMIT();
    HSTAGE(wsm_hw + 10240, 1); CP_COMMIT();

#pragma unroll 1
    for (int kc2 = 0; kc2 < 16; kc2++) {
        CP_WAIT(1);
        __syncwarp();
        uint32_t coff = wbase_off + (kc2 & 1) * 10240;
        HCONS(coff, 2 * kc2);
        HCONS(coff, 2 * kc2 + 1);
        if (kc2 < 14)
            HSTAGE(wsm_hw + ((kc2 & 1) ? 10240u : 0u), kc2 + 2);
        CP_COMMIT();   // empty group when no stage issued keeps wait(1) exact
    }
#undef HSTAGE
#undef HCONS

    // epilogue: bias + scale + fp16 pack + fragment scatter
    const int s0 = lane >> 2;           // sample rows s0, s0+8
#pragma unroll
    for (int t = 0; t < 8; t++) {
#pragma unroll
        for (int j = 0; j < 2; j++) {
            int k = kbase + t * 8 + (lane & 3) * 2 + j;
            float bk = bias[k];
            float scale; bool isBias;
            int fel = map_fel(k, scale, isBias);
            float v0 = acc[t][j]     + bk;   // sample s0
            float v1 = acc[t][j + 2] + bk;   // sample s0+8
            if (isBias) {
                g_bias[s0 * 512 + (k - 53248)]       = v0;
                g_bias[(s0 + 8) * 512 + (k - 53248)] = v1;
            } else {
                g_wh[(size_t)s0 * WS + fel]       = __float2half_rn(v0 * scale);
                g_wh[(size_t)(s0 + 8) * WS + fel] = __float2half_rn(v1 * scale);
            }
        }
    }
}

// ============================================================
// Kernel B (reverted to proven R12 structure, 86.7 us): mma.sync
// fused block, fp16 single-term weights, M=32 per warp, 2-nt
// transient accumulators, per-sample grid.
// ============================================================
template <int KT>
__device__ __forceinline__ void layer_fused(
    const uint32_t (*A0)[4], const uint32_t (*A1)[4],
    uint32_t (*N0)[4], uint32_t (*N1)[4],
    const char* __restrict__ sm, int bOff,
    const float* __restrict__ bsm, int lane, int tig)
{
#pragma unroll
    for (int c = 0; c < 8; c++) {        // chunk = 2 nt = 16 channels
        float D[2][2][4];
#pragma unroll
        for (int j = 0; j < 2; j++) {
            int nt = c * 2 + j;
            float b0 = bsm[nt * 8 + tig * 2];
            float b1 = bsm[nt * 8 + tig * 2 + 1];
#pragma unroll
            for (int m = 0; m < 2; m++) {
                D[m][j][0] = b0; D[m][j][1] = b1;
                D[m][j][2] = b0; D[m][j][3] = b1;
            }
        }
#pragma unroll
        for (int kt = 0; kt < KT; kt++) {
            uint2 bf[2];
#pragma unroll
            for (int j = 0; j < 2; j++) {
                int fo = (((c * 2 + j) * KT + kt) * 32 + lane) * 8;
                bf[j] = *(const uint2*)(sm + bOff + fo);
            }
#pragma unroll
            for (int j = 0; j < 2; j++) {
                mma16816(D[0][j], A0[kt], bf[j].x, bf[j].y);
                mma16816(D[1][j], A1[kt], bf[j].x, bf[j].y);
            }
        }
#pragma unroll
        for (int m = 0; m < 2; m++) {
            uint32_t (*N)[4] = m ? N1 : N0;
            N[c][0] = pack_f16x2(fmaxf(D[m][0][0], 0.f), fmaxf(D[m][0][1], 0.f));
            N[c][1] = pack_f16x2(fmaxf(D[m][0][2], 0.f), fmaxf(D[m][0][3], 0.f));
            N[c][2] = pack_f16x2(fmaxf(D[m][1][0], 0.f), fmaxf(D[m][1][1], 0.f));
            N[c][3] = pack_f16x2(fmaxf(D[m][1][2], 0.f), fmaxf(D[m][1][3], 0.f));
        }
    }
}

__global__ __launch_bounds__(256, 1) void conv_kernel(
    const float* __restrict__ x, float* __restrict__ out)
{
    extern __shared__ __align__(16) char smem[];
    const float* bsm = (const float*)(smem + WS * 2);

    const int tid = threadIdx.x;
    const int w = tid >> 5, lane = tid & 31;
    const int gid = lane >> 2, tig = lane & 3;
    const int b  = blockIdx.x / 9;
    const int cs = blockIdx.x % 9;

    // stage all fragment-ordered weights (106496 B) + biases (2 KB)
    {
        const uint4* src = (const uint4*)(g_wh + (size_t)b * WS);
        uint4* dst = (uint4*)smem;
        for (int i = tid; i < WS / 8; i += 256) dst[i] = src[i];
        const float4* bsrc = (const float4*)(g_bias + b * 512);
        float4* bdst = (float4*)(smem + WS * 2);
        if (tid < 128) bdst[tid] = bsrc[tid];
    }
    __syncthreads();

    const float* xb = x + (size_t)b * FIN * HW;
    float* ob = out + (size_t)b * FOUT * HW;

    uint32_t X[2][4][4];
    uint32_t Abuf[2][2][8][4];   // ping-pong [pp][half][kt][4]

    for (int t = cs; t < 64; t += 9) {
        const int base = t * 256 + w * 32;

        // ---- load x as fp16 A fragments for both m16 halves ----
#pragma unroll
        for (int m = 0; m < 2; m++) {
            const int px_lo = base + m * 16 + gid;
            const int px_hi = px_lo + 8;
#pragma unroll
            for (int kt = 0; kt < 4; kt++) {
                const float* xp = xb + (size_t)(kt * 16 + tig * 2) * HW;
                X[m][kt][0] = pack_f16x2(xp[px_lo],          xp[HW + px_lo]);
                X[m][kt][1] = pack_f16x2(xp[px_hi],          xp[HW + px_hi]);
                X[m][kt][2] = pack_f16x2(xp[8 * HW + px_lo], xp[9 * HW + px_lo]);
                X[m][kt][3] = pack_f16x2(xp[8 * HW + px_hi], xp[9 * HW + px_hi]);
            }
        }

        layer_fused<4>(X[0], X[1], Abuf[0][0], Abuf[0][1],
                       smem, WIN_O * 2, bsm + 0, lane, tig);
        layer_fused<8>(Abuf[0][0], Abuf[0][1], Abuf[1][0], Abuf[1][1],
                       smem, WMIDA_O * 2, bsm + 128, lane, tig);
        layer_fused<8>(Abuf[1][0], Abuf[1][1], Abuf[0][0], Abuf[0][1],
                       smem, WMIDB_O * 2, bsm + 256, lane, tig);

        // ---- out layer: Wout @ h + Wshort @ x ----
#pragma unroll
        for (int c = 0; c < 4; c++) {
            float D[2][2][4];
#pragma unroll
            for (int j = 0; j < 2; j++) {
                int ch = (c * 2 + j) * 8 + tig * 2;
                float b0 = bsm[384 + ch]     + bsm[448 + ch];
                float b1 = bsm[384 + ch + 1] + bsm[448 + ch + 1];
#pragma unroll
                for (int m = 0; m < 2; m++) {
                    D[m][j][0] = b0; D[m][j][1] = b1;
                    D[m][j][2] = b0; D[m][j][3] = b1;
                }
            }
#pragma unroll
            for (int kt = 0; kt < 8; kt++) {
                uint2 bf[2];
#pragma unroll
                for (int j = 0; j < 2; j++) {
                    int fo = (((c * 2 + j) * 8 + kt) * 32 + lane) * 8;
                    bf[j] = *(const uint2*)(smem + WOUT_O * 2 + fo);
                }
#pragma unroll
                for (int j = 0; j < 2; j++) {
                    mma16816(D[0][j], Abuf[0][0][kt], bf[j].x, bf[j].y);
                    mma16816(D[1][j], Abuf[0][1][kt], bf[j].x, bf[j].y);
                }
            }
#pragma unroll
            for (int kt = 0; kt < 4; kt++) {
                uint2 bf[2];
#pragma unroll
                for (int j = 0; j < 2; j++) {
                    int fo = (((c * 2 + j) * 4 + kt) * 32 + lane) * 8;
                    bf[j] = *(const uint2*)(smem + WSH_O * 2 + fo);
                }
#pragma unroll
                for (int j = 0; j < 2; j++) {
                    mma16816(D[0][j], X[0][kt], bf[j].x, bf[j].y);
                    mma16816(D[1][j], X[1][kt], bf[j].x, bf[j].y);
                }
            }
#pragma unroll
            for (int m = 0; m < 2; m++) {
                const int px_lo = base + m * 16 + gid;
                const int px_hi = px_lo + 8;
#pragma unroll
                for (int j = 0; j < 2; j++) {
                    int ch = (c * 2 + j) * 8 + tig * 2;
                    float* op = ob + (size_t)ch * HW;
                    op[px_lo]      = D[m][j][0];
                    op[HW + px_lo] = D[m][j][1];
                    op[px_hi]      = D[m][j][2];
                    op[HW + px_hi] = D[m][j][3];
                }
            }
        }
    }
}

// ============================================================
extern "C" void kernel_launch(void* const* d_in, const int* in_sizes, int n_in,
                              void* d_out, int out_size)
{
    (void)in_sizes; (void)n_in; (void)out_size;
    const float* x    = (const float*)d_in[0];
    const float* lat  = (const float*)d_in[1];
    const float* W    = (const float*)d_in[2];
    const float* bias = (const float*)d_in[3];
    float* out = (float*)d_out;

    cudaFuncSetAttribute(hyper_kernel,
                         cudaFuncAttributeMaxDynamicSharedMemorySize, 155648);
    hyper_kernel<<<148, 192, 155648>>>(lat, W, bias);

    cudaFuncSetAttribute(conv_kernel,
                         cudaFuncAttributeMaxDynamicSharedMemorySize, 110592);
    conv_kernel<<<16 * 9, 256, 110592>>>(x, out);
}

// round 15
// speedup vs baseline: 1.1286x; 1.0285x over previous
#include <cuda_runtime.h>
#include <cuda_fp16.h>
#include <cstdint>

#define FIN   64
#define FOUT  64
#define FH    128
#define LATD  512
#define NB    16
#define HW    16384
#define KTOT  53760
#define WS    53248   // fp16 elements of packed weights per sample (single-term)

// per-sample fp16 element offsets of fragment-ordered weight buffers
#define WIN_O   0        // O=128 I=64  (8192 ele)
#define WMIDA_O 8192     // O=128 I=128 (16384)
#define WMIDB_O 24576    // O=128 I=128 (16384)
#define WOUT_O  40960    // O=64 I=128  (8192)
#define WSH_O   49152    // O=64 I=64   (4096)

__device__ __align__(16) __half g_wh[NB * WS];
__device__ __align__(16) float g_bias[NB * 512];

// ---------------- helpers ----------------
__device__ __forceinline__ uint32_t pack_f16x2(float f0, float f1) {
    uint32_t r;
    asm("cvt.rn.f16x2.f32 %0, %1, %2;" : "=r"(r) : "f"(f1), "f"(f0));
    return r;
}
__device__ __forceinline__ void split2(float f0, float f1, uint32_t& hi, uint32_t& lo) {
    asm("cvt.rn.f16x2.f32 %0, %1, %2;" : "=r"(hi) : "f"(f1), "f"(f0));
    __half2 h = *(__half2*)&hi;
    float r0 = f0 - __low2float(h), r1 = f1 - __high2float(h);
    asm("cvt.rn.f16x2.f32 %0, %1, %2;" : "=r"(lo) : "f"(r1), "f"(r0));
}
__device__ __forceinline__ uint32_t smem_u32(const void* p) {
    uint32_t a;
    asm("{ .reg .u64 t; cvta.to.shared.u64 t, %1; cvt.u32.u64 %0, t; }" : "=r"(a) : "l"(p));
    return a;
}

__device__ __forceinline__ void mma16816(float d[4],
    const uint32_t a[4], uint32_t b0, uint32_t b1)
{
    asm volatile(
        "mma.sync.aligned.m16n8k16.row.col.f32.f16.f16.f32 "
        "{%0,%1,%2,%3}, {%4,%5,%6,%7}, {%8,%9}, {%0,%1,%2,%3};"
        : "+f"(d[0]), "+f"(d[1]), "+f"(d[2]), "+f"(d[3])
        : "r"(a[0]), "r"(a[1]), "r"(a[2]), "r"(a[3]), "r"(b0), "r"(b1));
}

#define CP_ASYNC16(dst, src) \
    asm volatile("cp.async.cg.shared.global [%0], [%1], 16;" :: "r"(dst), "l"(src) : "memory")
#define CP_COMMIT() asm volatile("cp.async.commit_group;" ::: "memory")
#define CP_WAIT(n)  asm volatile("cp.async.wait_group %0;" :: "n"(n) : "memory")

// map hypernet row k -> fragment element index / bias flag / scale
__device__ __forceinline__ int map_fel(int k, float& scale, bool& isBias) {
    const float RS128 = 0.08838834764831845f;
    const float RS64  = 0.125f;
    int o, i, I, base;
    isBias = false;
    if (k < 8192)       { o = k >> 6;            i = k & 63;  I = 64;  base = WIN_O;   scale = RS128; }
    else if (k < 24576) { int x = k - 8192;  o = x >> 7; i = x & 127; I = 128; base = WMIDA_O; scale = RS128; }
    else if (k < 40960) { int x = k - 24576; o = x >> 7; i = x & 127; I = 128; base = WMIDB_O; scale = RS128; }
    else if (k < 49152) { int x = k - 40960; o = x >> 7; i = x & 127; I = 128; base = WOUT_O;  scale = RS64; }
    else if (k < 53248) { int x = k - 49152; o = x >> 6; i = x & 63;  I = 64;  base = WSH_O;   scale = RS64; }
    else { isBias = true; scale = 1.f; return 0; }
    int KT = I / 16;
    int nt = o >> 3, kt = i >> 4;
    int tl = (o & 7) * 4 + ((i & 7) >> 1);
    int el = (((i >> 3) & 1) << 1) | (i & 1);
    return base + ((nt * KT + kt) * 32 + tl) * 4 + el;
}

// ============================================================
// Kernel A: hypernetwork GEMM on tensor cores, cp.async-staged W.
// 148 CTAs x 384 thr = 12 warps (3/SMSP), 32 k-rows per warp
// (guard g<1680). Double-buffered per-warp smem stages, 160B pad.
// ============================================================
__global__ __launch_bounds__(384) void hyper_kernel(
    const float* __restrict__ lat,
    const float* __restrict__ Wm,
    const float* __restrict__ bias)
{
    extern __shared__ __align__(16) char hsm[];
    uint4* sAhi = (uint4*)hsm;               // [32][32] = 16 KB
    uint4* sAlo = (uint4*)(hsm + 16384);     // 16 KB
    // W stage: 12 warps x 2 stages x 32 rows x 160 B = 122880 B at +32768

    const int tid  = threadIdx.x;
    const int lane = tid & 31;
    const int w    = tid >> 5;

    // stage lat fragments hi/lo (all 32 k-chunks)
    for (int idx = tid; idx < 1024; idx += 384) {
        int kc = idx >> 5, ln = idx & 31;
        int r = ln >> 2, c = kc * 16 + (ln & 3) * 2;
        uint32_t h[4], l[4];
        split2(lat[r * 512 + c],           lat[r * 512 + c + 1],           h[0], l[0]);
        split2(lat[(r + 8) * 512 + c],     lat[(r + 8) * 512 + c + 1],     h[1], l[1]);
        split2(lat[r * 512 + c + 8],       lat[r * 512 + c + 9],           h[2], l[2]);
        split2(lat[(r + 8) * 512 + c + 8], lat[(r + 8) * 512 + c + 9],     h[3], l[3]);
        sAhi[kc * 32 + ln] = make_uint4(h[0], h[1], h[2], h[3]);
        sAlo[kc * 32 + ln] = make_uint4(l[0], l[1], l[2], l[3]);
    }
    __syncthreads();

    const int g = blockIdx.x * 12 + w;
    if (g >= 1680) return;
    const int kbase = g * 32;
    const float* __restrict__ wrow = Wm + (size_t)kbase * 512;

    const uint32_t wbase_off = 32768 + w * 10240;      // byte offset in hsm
    const uint32_t wsm_hw    = smem_u32(hsm) + wbase_off;

    float acc[4][4];
#pragma unroll
    for (int t = 0; t < 4; t++) {
        acc[t][0] = 0.f; acc[t][1] = 0.f; acc[t][2] = 0.f; acc[t][3] = 0.f;
    }

    const int rrow = lane >> 2;
    const int tig  = lane & 3;

    // stage: 32 rows x 128 B (2 k-chunks) coalesced; 8 x 16B per lane
#define HSTAGE(DSTHW, KC2) do {                                              \
        const float* _s = wrow + (size_t)(lane >> 3) * 512                   \
                          + (KC2) * 32 + (lane & 7) * 4;                     \
        uint32_t _d = (DSTHW) + (lane >> 3) * 160 + (lane & 7) * 16;         \
        _Pragma("unroll")                                                    \
        for (int i = 0; i < 8; i++)                                          \
            CP_ASYNC16(_d + i * 4 * 160, _s + (size_t)i * 4 * 512);          \
    } while (0)

    // consume one k-chunk from staged smem
#define HCONS(COFF, KC) do {                                                 \
        uint4 ah4 = sAhi[(KC) * 32 + lane];                                  \
        uint4 al4 = sAlo[(KC) * 32 + lane];                                  \
        uint32_t Ah[4] = {ah4.x, ah4.y, ah4.z, ah4.w};                       \
        uint32_t Al[4] = {al4.x, al4.y, al4.z, al4.w};                       \
        const char* _c = hsm + (COFF) + ((KC) & 1) * 64 + rrow * 160 + tig * 8; \
        _Pragma("unroll")                                                    \
        for (int t = 0; t < 4; t++) {                                        \
            float2 w0 = *(const float2*)(_c + t * 8 * 160);                  \
            float2 w1 = *(const float2*)(_c + t * 8 * 160 + 32);             \
            uint32_t bh0, bl0, bh1, bl1;                                     \
            split2(w0.x, w0.y, bh0, bl0);                                    \
            split2(w1.x, w1.y, bh1, bl1);                                    \
            mma16816(acc[t], Ah, bh0, bh1);                                  \
            mma16816(acc[t], Al, bh0, bh1);                                  \
            mma16816(acc[t], Ah, bl0, bl1);                                  \
        }                                                                    \
    } while (0)

    HSTAGE(wsm_hw, 0);        CP_COMMIT();
    HSTAGE(wsm_hw + 5120, 1); CP_COMMIT();

#pragma unroll 1
    for (int kc2 = 0; kc2 < 16; kc2++) {
        CP_WAIT(1);
        __syncwarp();
        uint32_t coff = wbase_off + (kc2 & 1) * 5120;
        HCONS(coff, 2 * kc2);
        HCONS(coff, 2 * kc2 + 1);
        if (kc2 < 14)
            HSTAGE(wsm_hw + ((kc2 & 1) ? 5120u : 0u), kc2 + 2);
        CP_COMMIT();   // empty group when no stage issued keeps wait(1) exact
    }
#undef HSTAGE
#undef HCONS

    // epilogue: bias + scale + fp16 pack + fragment scatter
    const int s0 = lane >> 2;           // sample rows s0, s0+8
#pragma unroll
    for (int t = 0; t < 4; t++) {
#pragma unroll
        for (int j = 0; j < 2; j++) {
            int k = kbase + t * 8 + (lane & 3) * 2 + j;
            float bk = bias[k];
            float scale; bool isBias;
            int fel = map_fel(k, scale, isBias);
            float v0 = acc[t][j]     + bk;   // sample s0
            float v1 = acc[t][j + 2] + bk;   // sample s0+8
            if (isBias) {
                g_bias[s0 * 512 + (k - 53248)]       = v0;
                g_bias[(s0 + 8) * 512 + (k - 53248)] = v1;
            } else {
                g_wh[(size_t)s0 * WS + fel]       = __float2half_rn(v0 * scale);
                g_wh[(size_t)(s0 + 8) * WS + fel] = __float2half_rn(v1 * scale);
            }
        }
    }
}

// ============================================================
// Kernel B (frozen, 86.7 us): mma.sync fused block, fp16
// single-term weights, M=32 per warp, 2-nt transient accumulators,
// per-sample grid.
// ============================================================
template <int KT>
__device__ __forceinline__ void layer_fused(
    const uint32_t (*A0)[4], const uint32_t (*A1)[4],
    uint32_t (*N0)[4], uint32_t (*N1)[4],
    const char* __restrict__ sm, int bOff,
    const float* __restrict__ bsm, int lane, int tig)
{
#pragma unroll
    for (int c = 0; c < 8; c++) {        // chunk = 2 nt = 16 channels
        float D[2][2][4];
#pragma unroll
        for (int j = 0; j < 2; j++) {
            int nt = c * 2 + j;
            float b0 = bsm[nt * 8 + tig * 2];
            float b1 = bsm[nt * 8 + tig * 2 + 1];
#pragma unroll
            for (int m = 0; m < 2; m++) {
                D[m][j][0] = b0; D[m][j][1] = b1;
                D[m][j][2] = b0; D[m][j][3] = b1;
            }
        }
#pragma unroll
        for (int kt = 0; kt < KT; kt++) {
            uint2 bf[2];
#pragma unroll
            for (int j = 0; j < 2; j++) {
                int fo = (((c * 2 + j) * KT + kt) * 32 + lane) * 8;
                bf[j] = *(const uint2*)(sm + bOff + fo);
            }
#pragma unroll
            for (int j = 0; j < 2; j++) {
                mma16816(D[0][j], A0[kt], bf[j].x, bf[j].y);
                mma16816(D[1][j], A1[kt], bf[j].x, bf[j].y);
            }
        }
#pragma unroll
        for (int m = 0; m < 2; m++) {
            uint32_t (*N)[4] = m ? N1 : N0;
            N[c][0] = pack_f16x2(fmaxf(D[m][0][0], 0.f), fmaxf(D[m][0][1], 0.f));
            N[c][1] = pack_f16x2(fmaxf(D[m][0][2], 0.f), fmaxf(D[m][0][3], 0.f));
            N[c][2] = pack_f16x2(fmaxf(D[m][1][0], 0.f), fmaxf(D[m][1][1], 0.f));
            N[c][3] = pack_f16x2(fmaxf(D[m][1][2], 0.f), fmaxf(D[m][1][3], 0.f));
        }
    }
}

__global__ __launch_bounds__(256, 1) void conv_kernel(
    const float* __restrict__ x, float* __restrict__ out)
{
    extern __shared__ __align__(16) char smem[];
    const float* bsm = (const float*)(smem + WS * 2);

    const int tid = threadIdx.x;
    const int w = tid >> 5, lane = tid & 31;
    const int gid = lane >> 2, tig = lane & 3;
    const int b  = blockIdx.x / 9;
    const int cs = blockIdx.x % 9;

    // stage all fragment-ordered weights (106496 B) + biases (2 KB)
    {
        const uint4* src = (const uint4*)(g_wh + (size_t)b * WS);
        uint4* dst = (uint4*)smem;
        for (int i = tid; i < WS / 8; i += 256) dst[i] = src[i];
        const float4* bsrc = (const float4*)(g_bias + b * 512);
        float4* bdst = (float4*)(smem + WS * 2);
        if (tid < 128) bdst[tid] = bsrc[tid];
    }
    __syncthreads();

    const float* xb = x + (size_t)b * FIN * HW;
    float* ob = out + (size_t)b * FOUT * HW;

    uint32_t X[2][4][4];
    uint32_t Abuf[2][2][8][4];   // ping-pong [pp][half][kt][4]

    for (int t = cs; t < 64; t += 9) {
        const int base = t * 256 + w * 32;

        // ---- load x as fp16 A fragments for both m16 halves ----
#pragma unroll
        for (int m = 0; m < 2; m++) {
            const int px_lo = base + m * 16 + gid;
            const int px_hi = px_lo + 8;
#pragma unroll
            for (int kt = 0; kt < 4; kt++) {
                const float* xp = xb + (size_t)(kt * 16 + tig * 2) * HW;
                X[m][kt][0] = pack_f16x2(xp[px_lo],          xp[HW + px_lo]);
                X[m][kt][1] = pack_f16x2(xp[px_hi],          xp[HW + px_hi]);
                X[m][kt][2] = pack_f16x2(xp[8 * HW + px_lo], xp[9 * HW + px_lo]);
                X[m][kt][3] = pack_f16x2(xp[8 * HW + px_hi], xp[9 * HW + px_hi]);
            }
        }

        layer_fused<4>(X[0], X[1], Abuf[0][0], Abuf[0][1],
                       smem, WIN_O * 2, bsm + 0, lane, tig);
        layer_fused<8>(Abuf[0][0], Abuf[0][1], Abuf[1][0], Abuf[1][1],
                       smem, WMIDA_O * 2, bsm + 128, lane, tig);
        layer_fused<8>(Abuf[1][0], Abuf[1][1], Abuf[0][0], Abuf[0][1],
                       smem, WMIDB_O * 2, bsm + 256, lane, tig);

        // ---- out layer: Wout @ h + Wshort @ x ----
#pragma unroll
        for (int c = 0; c < 4; c++) {
            float D[2][2][4];
#pragma unroll
            for (int j = 0; j < 2; j++) {
                int ch = (c * 2 + j) * 8 + tig * 2;
                float b0 = bsm[384 + ch]     + bsm[448 + ch];
                float b1 = bsm[384 + ch + 1] + bsm[448 + ch + 1];
#pragma unroll
                for (int m = 0; m < 2; m++) {
                    D[m][j][0] = b0; D[m][j][1] = b1;
                    D[m][j][2] = b0; D[m][j][3] = b1;
                }
            }
#pragma unroll
            for (int kt = 0; kt < 8; kt++) {
                uint2 bf[2];
#pragma unroll
                for (int j = 0; j < 2; j++) {
                    int fo = (((c * 2 + j) * 8 + kt) * 32 + lane) * 8;
                    bf[j] = *(const uint2*)(smem + WOUT_O * 2 + fo);
                }
#pragma unroll
                for (int j = 0; j < 2; j++) {
                    mma16816(D[0][j], Abuf[0][0][kt], bf[j].x, bf[j].y);
                    mma16816(D[1][j], Abuf[0][1][kt], bf[j].x, bf[j].y);
                }
            }
#pragma unroll
            for (int kt = 0; kt < 4; kt++) {
                uint2 bf[2];
#pragma unroll
                for (int j = 0; j < 2; j++) {
                    int fo = (((c * 2 + j) * 4 + kt) * 32 + lane) * 8;
                    bf[j] = *(const uint2*)(smem + WSH_O * 2 + fo);
                }
#pragma unroll
                for (int j = 0; j < 2; j++) {
                    mma16816(D[0][j], X[0][kt], bf[j].x, bf[j].y);
                    mma16816(D[1][j], X[1][kt], bf[j].x, bf[j].y);
                }
            }
#pragma unroll
            for (int m = 0; m < 2; m++) {
                const int px_lo = base + m * 16 + gid;
                const int px_hi = px_lo + 8;
#pragma unroll
                for (int j = 0; j < 2; j++) {
                    int ch = (c * 2 + j) * 8 + tig * 2;
                    float* op = ob + (size_t)ch * HW;
                    op[px_lo]      = D[m][j][0];
                    op[HW + px_lo] = D[m][j][1];
                    op[px_hi]      = D[m][j][2];
                    op[HW + px_hi] = D[m][j][3];
                }
            }
        }
    }
}

// ============================================================
extern "C" void kernel_launch(void* const* d_in, const int* in_sizes, int n_in,
                              void* d_out, int out_size)
{
    (void)in_sizes; (void)n_in; (void)out_size;
    const float* x    = (const float*)d_in[0];
    const float* lat  = (const float*)d_in[1];
    const float* W    = (const float*)d_in[2];
    const float* bias = (const float*)d_in[3];
    float* out = (float*)d_out;

    cudaFuncSetAttribute(hyper_kernel,
                         cudaFuncAttributeMaxDynamicSharedMemorySize, 155648);
    hyper_kernel<<<148, 384, 155648>>>(lat, W, bias);

    cudaFuncSetAttribute(conv_kernel,
                         cudaFuncAttributeMaxDynamicSharedMemorySize, 110592);
    conv_kernel<<<16 * 9, 256, 110592>>>(x, out);
}

// round 16
// speedup vs baseline: 1.1650x; 1.0323x over previous
#include <cuda_runtime.h>
#include <cuda_fp16.h>
#include <cstdint>

#define FIN   64
#define FOUT  64
#define FH    128
#define LATD  512
#define NB    16
#define HW    16384
#define KTOT  53760
#define WS    53248   // fp16 elements of packed weights per sample (single-term)

// per-sample fp16 element offsets of fragment-ordered weight buffers
#define WIN_O   0        // O=128 I=64  (8192 ele)
#define WMIDA_O 8192     // O=128 I=128 (16384)
#define WMIDB_O 24576    // O=128 I=128 (16384)
#define WOUT_O  40960    // O=64 I=128  (8192)
#define WSH_O   49152    // O=64 I=64   (4096)

__device__ __align__(16) __half g_wh[NB * WS];
__device__ __align__(16) float g_bias[NB * 512];

// ---------------- helpers ----------------
__device__ __forceinline__ uint32_t pack_f16x2(float f0, float f1) {
    uint32_t r;
    asm("cvt.rn.f16x2.f32 %0, %1, %2;" : "=r"(r) : "f"(f1), "f"(f0));
    return r;
}
__device__ __forceinline__ void split2(float f0, float f1, uint32_t& hi, uint32_t& lo) {
    asm("cvt.rn.f16x2.f32 %0, %1, %2;" : "=r"(hi) : "f"(f1), "f"(f0));
    __half2 h = *(__half2*)&hi;
    float r0 = f0 - __low2float(h), r1 = f1 - __high2float(h);
    asm("cvt.rn.f16x2.f32 %0, %1, %2;" : "=r"(lo) : "f"(r1), "f"(r0));
}
__device__ __forceinline__ uint32_t smem_u32(const void* p) {
    uint32_t a;
    asm("{ .reg .u64 t; cvta.to.shared.u64 t, %1; cvt.u32.u64 %0, t; }" : "=r"(a) : "l"(p));
    return a;
}

__device__ __forceinline__ void mma16816(float d[4],
    const uint32_t a[4], uint32_t b0, uint32_t b1)
{
    asm volatile(
        "mma.sync.aligned.m16n8k16.row.col.f32.f16.f16.f32 "
        "{%0,%1,%2,%3}, {%4,%5,%6,%7}, {%8,%9}, {%0,%1,%2,%3};"
        : "+f"(d[0]), "+f"(d[1]), "+f"(d[2]), "+f"(d[3])
        : "r"(a[0]), "r"(a[1]), "r"(a[2]), "r"(a[3]), "r"(b0), "r"(b1));
}

#define CP_ASYNC16(dst, src) \
    asm volatile("cp.async.cg.shared.global [%0], [%1], 16;" :: "r"(dst), "l"(src) : "memory")
#define CP_COMMIT() asm volatile("cp.async.commit_group;" ::: "memory")
#define CP_WAIT(n)  asm volatile("cp.async.wait_group %0;" :: "n"(n) : "memory")

// map hypernet row k -> fragment element index (j-pair interleaved layout)
// fel = base + (c2*KT + kt)*256 + tl*8 + j*4 + el
__device__ __forceinline__ int map_fel(int k, float& scale, bool& isBias) {
    const float RS128 = 0.08838834764831845f;
    const float RS64  = 0.125f;
    int o, i, I, base;
    isBias = false;
    if (k < 8192)       { o = k >> 6;            i = k & 63;  I = 64;  base = WIN_O;   scale = RS128; }
    else if (k < 24576) { int x = k - 8192;  o = x >> 7; i = x & 127; I = 128; base = WMIDA_O; scale = RS128; }
    else if (k < 40960) { int x = k - 24576; o = x >> 7; i = x & 127; I = 128; base = WMIDB_O; scale = RS128; }
    else if (k < 49152) { int x = k - 40960; o = x >> 7; i = x & 127; I = 128; base = WOUT_O;  scale = RS64; }
    else if (k < 53248) { int x = k - 49152; o = x >> 6; i = x & 63;  I = 64;  base = WSH_O;   scale = RS64; }
    else { isBias = true; scale = 1.f; return 0; }
    int KT = I / 16;
    int nt = o >> 3, kt = i >> 4;
    int c2 = nt >> 1, jj = nt & 1;
    int tl = (o & 7) * 4 + ((i & 7) >> 1);
    int el = (((i >> 3) & 1) << 1) | (i & 1);
    return base + (c2 * KT + kt) * 256 + tl * 8 + jj * 4 + el;
}

// ============================================================
// Kernel A: hypernetwork GEMM on tensor cores, cp.async-staged W.
// 148 CTAs x 384 thr (3 warps/SMSP), 32 k-rows per warp.
// Epilogue stores __half2 pairs (adjacent fel) -> 2x fewer, wider STG.
// ============================================================
__global__ __launch_bounds__(384) void hyper_kernel(
    const float* __restrict__ lat,
    const float* __restrict__ Wm,
    const float* __restrict__ bias)
{
    extern __shared__ __align__(16) char hsm[];
    uint4* sAhi = (uint4*)hsm;               // [32][32] = 16 KB
    uint4* sAlo = (uint4*)(hsm + 16384);     // 16 KB
    // W stage: 12 warps x 2 stages x 32 rows x 160 B = 122880 B at +32768

    const int tid  = threadIdx.x;
    const int lane = tid & 31;
    const int w    = tid >> 5;

    for (int idx = tid; idx < 1024; idx += 384) {
        int kc = idx >> 5, ln = idx & 31;
        int r = ln >> 2, c = kc * 16 + (ln & 3) * 2;
        uint32_t h[4], l[4];
        split2(lat[r * 512 + c],           lat[r * 512 + c + 1],           h[0], l[0]);
        split2(lat[(r + 8) * 512 + c],     lat[(r + 8) * 512 + c + 1],     h[1], l[1]);
        split2(lat[r * 512 + c + 8],       lat[r * 512 + c + 9],           h[2], l[2]);
        split2(lat[(r + 8) * 512 + c + 8], lat[(r + 8) * 512 + c + 9],     h[3], l[3]);
        sAhi[kc * 32 + ln] = make_uint4(h[0], h[1], h[2], h[3]);
        sAlo[kc * 32 + ln] = make_uint4(l[0], l[1], l[2], l[3]);
    }
    __syncthreads();

    const int g = blockIdx.x * 12 + w;
    if (g >= 1680) return;
    const int kbase = g * 32;
    const float* __restrict__ wrow = Wm + (size_t)kbase * 512;

    const uint32_t wbase_off = 32768 + w * 10240;
    const uint32_t wsm_hw    = smem_u32(hsm) + wbase_off;

    float acc[4][4];
#pragma unroll
    for (int t = 0; t < 4; t++) {
        acc[t][0] = 0.f; acc[t][1] = 0.f; acc[t][2] = 0.f; acc[t][3] = 0.f;
    }

    const int rrow = lane >> 2;
    const int tig  = lane & 3;

#define HSTAGE(DSTHW, KC2) do {                                              \
        const float* _s = wrow + (size_t)(lane >> 3) * 512                   \
                          + (KC2) * 32 + (lane & 7) * 4;                     \
        uint32_t _d = (DSTHW) + (lane >> 3) * 160 + (lane & 7) * 16;         \
        _Pragma("unroll")                                                    \
        for (int i = 0; i < 8; i++)                                          \
            CP_ASYNC16(_d + i * 4 * 160, _s + (size_t)i * 4 * 512);          \
    } while (0)

#define HCONS(COFF, KC) do {                                                 \
        uint4 ah4 = sAhi[(KC) * 32 + lane];                                  \
        uint4 al4 = sAlo[(KC) * 32 + lane];                                  \
        uint32_t Ah[4] = {ah4.x, ah4.y, ah4.z, ah4.w};                       \
        uint32_t Al[4] = {al4.x, al4.y, al4.z, al4.w};                       \
        const char* _c = hsm + (COFF) + ((KC) & 1) * 64 + rrow * 160 + tig * 8; \
        _Pragma("unroll")                                                    \
        for (int t = 0; t < 4; t++) {                                        \
            float2 w0 = *(const float2*)(_c + t * 8 * 160);                  \
            float2 w1 = *(const float2*)(_c + t * 8 * 160 + 32);             \
            uint32_t bh0, bl0, bh1, bl1;                                     \
            split2(w0.x, w0.y, bh0, bl0);                                    \
            split2(w1.x, w1.y, bh1, bl1);                                    \
            mma16816(acc[t], Ah, bh0, bh1);                                  \
            mma16816(acc[t], Al, bh0, bh1);                                  \
            mma16816(acc[t], Ah, bl0, bl1);                                  \
        }                                                                    \
    } while (0)

    HSTAGE(wsm_hw, 0);        CP_COMMIT();
    HSTAGE(wsm_hw + 5120, 1); CP_COMMIT();

#pragma unroll 1
    for (int kc2 = 0; kc2 < 16; kc2++) {
        CP_WAIT(1);
        __syncwarp();
        uint32_t coff = wbase_off + (kc2 & 1) * 5120;
        HCONS(coff, 2 * kc2);
        HCONS(coff, 2 * kc2 + 1);
        if (kc2 < 14)
            HSTAGE(wsm_hw + ((kc2 & 1) ? 5120u : 0u), kc2 + 2);
        CP_COMMIT();
    }
#undef HSTAGE
#undef HCONS

    // epilogue: bias + scale + paired __half2 stores (k even/odd adjacent)
    const int s0 = lane >> 2;           // sample rows s0, s0+8
#pragma unroll
    for (int t = 0; t < 4; t++) {
        int k0 = kbase + t * 8 + (lane & 3) * 2;   // even k
        float bk0 = bias[k0], bk1 = bias[k0 + 1];
        float scale; bool isBias;
        int fel = map_fel(k0, scale, isBias);
        float a0 = acc[t][0] + bk0, a1 = acc[t][1] + bk1;   // sample s0
        float b0 = acc[t][2] + bk0, b1 = acc[t][3] + bk1;   // sample s0+8
        if (isBias) {
            g_bias[s0 * 512 + (k0 - 53248)]           = a0;
            g_bias[s0 * 512 + (k0 - 53248) + 1]       = a1;
            g_bias[(s0 + 8) * 512 + (k0 - 53248)]     = b0;
            g_bias[(s0 + 8) * 512 + (k0 - 53248) + 1] = b1;
        } else {
            uint32_t p0 = pack_f16x2(a0 * scale, a1 * scale);
            uint32_t p1 = pack_f16x2(b0 * scale, b1 * scale);
            *(uint32_t*)(g_wh + (size_t)s0 * WS + fel)       = p0;
            *(uint32_t*)(g_wh + (size_t)(s0 + 8) * WS + fel) = p1;
        }
    }
}

// ============================================================
// Kernel B: mma.sync fused block, fp16 single-term weights,
// M=32 per warp, j-pair-interleaved fragments -> single LDS.128
// per (c,kt), 2-nt transient accumulators, per-sample grid.
// ============================================================
template <int KT>
__device__ __forceinline__ void layer_fused(
    const uint32_t (*A0)[4], const uint32_t (*A1)[4],
    uint32_t (*N0)[4], uint32_t (*N1)[4],
    const char* __restrict__ sm, int bOff,
    const float* __restrict__ bsm, int lane, int tig)
{
#pragma unroll
    for (int c = 0; c < 8; c++) {        // chunk = 2 nt = 16 channels
        float D[2][2][4];
#pragma unroll
        for (int j = 0; j < 2; j++) {
            int nt = c * 2 + j;
            float b0 = bsm[nt * 8 + tig * 2];
            float b1 = bsm[nt * 8 + tig * 2 + 1];
#pragma unroll
            for (int m = 0; m < 2; m++) {
                D[m][j][0] = b0; D[m][j][1] = b1;
                D[m][j][2] = b0; D[m][j][3] = b1;
            }
        }
#pragma unroll
        for (int kt = 0; kt < KT; kt++) {
            uint4 bf = *(const uint4*)(sm + bOff + ((c * KT + kt) * 32 + lane) * 16);
            mma16816(D[0][0], A0[kt], bf.x, bf.y);
            mma16816(D[1][0], A1[kt], bf.x, bf.y);
            mma16816(D[0][1], A0[kt], bf.z, bf.w);
            mma16816(D[1][1], A1[kt], bf.z, bf.w);
        }
#pragma unroll
        for (int m = 0; m < 2; m++) {
            uint32_t (*N)[4] = m ? N1 : N0;
            N[c][0] = pack_f16x2(fmaxf(D[m][0][0], 0.f), fmaxf(D[m][0][1], 0.f));
            N[c][1] = pack_f16x2(fmaxf(D[m][0][2], 0.f), fmaxf(D[m][0][3], 0.f));
            N[c][2] = pack_f16x2(fmaxf(D[m][1][0], 0.f), fmaxf(D[m][1][1], 0.f));
            N[c][3] = pack_f16x2(fmaxf(D[m][1][2], 0.f), fmaxf(D[m][1][3], 0.f));
        }
    }
}

__global__ __launch_bounds__(256, 1) void conv_kernel(
    const float* __restrict__ x, float* __restrict__ out)
{
    extern __shared__ __align__(16) char smem[];
    const float* bsm = (const float*)(smem + WS * 2);

    const int tid = threadIdx.x;
    const int w = tid >> 5, lane = tid & 31;
    const int gid = lane >> 2, tig = lane & 3;
    const int b  = blockIdx.x / 9;
    const int cs = blockIdx.x % 9;

    // stage all fragment-ordered weights (106496 B) + biases (2 KB)
    {
        const uint4* src = (const uint4*)(g_wh + (size_t)b * WS);
        uint4* dst = (uint4*)smem;
        for (int i = tid; i < WS / 8; i += 256) dst[i] = src[i];
        const float4* bsrc = (const float4*)(g_bias + b * 512);
        float4* bdst = (float4*)(smem + WS * 2);
        if (tid < 128) bdst[tid] = bsrc[tid];
    }
    __syncthreads();

    const float* xb = x + (size_t)b * FIN * HW;
    float* ob = out + (size_t)b * FOUT * HW;

    uint32_t X[2][4][4];
    uint32_t Abuf[2][2][8][4];   // ping-pong [pp][half][kt][4]

    for (int t = cs; t < 64; t += 9) {
        const int base = t * 256 + w * 32;

        // ---- load x as fp16 A fragments for both m16 halves ----
#pragma unroll
        for (int m = 0; m < 2; m++) {
            const int px_lo = base + m * 16 + gid;
            const int px_hi = px_lo + 8;
#pragma unroll
            for (int kt = 0; kt < 4; kt++) {
                const float* xp = xb + (size_t)(kt * 16 + tig * 2) * HW;
                X[m][kt][0] = pack_f16x2(xp[px_lo],          xp[HW + px_lo]);
                X[m][kt][1] = pack_f16x2(xp[px_hi],          xp[HW + px_hi]);
                X[m][kt][2] = pack_f16x2(xp[8 * HW + px_lo], xp[9 * HW + px_lo]);
                X[m][kt][3] = pack_f16x2(xp[8 * HW + px_hi], xp[9 * HW + px_hi]);
            }
        }

        layer_fused<4>(X[0], X[1], Abuf[0][0], Abuf[0][1],
                       smem, WIN_O * 2, bsm + 0, lane, tig);
        layer_fused<8>(Abuf[0][0], Abuf[0][1], Abuf[1][0], Abuf[1][1],
                       smem, WMIDA_O * 2, bsm + 128, lane, tig);
        layer_fused<8>(Abuf[1][0], Abuf[1][1], Abuf[0][0], Abuf[0][1],
                       smem, WMIDB_O * 2, bsm + 256, lane, tig);

        // ---- out layer: Wout @ h + Wshort @ x ----
#pragma unroll
        for (int c = 0; c < 4; c++) {
            float D[2][2][4];
#pragma unroll
            for (int j = 0; j < 2; j++) {
                int ch = (c * 2 + j) * 8 + tig * 2;
                float b0 = bsm[384 + ch]     + bsm[448 + ch];
                float b1 = bsm[384 + ch + 1] + bsm[448 + ch + 1];
#pragma unroll
                for (int m = 0; m < 2; m++) {
                    D[m][j][0] = b0; D[m][j][1] = b1;
                    D[m][j][2] = b0; D[m][j][3] = b1;
                }
            }
#pragma unroll
            for (int kt = 0; kt < 8; kt++) {
                uint4 bf = *(const uint4*)(smem + WOUT_O * 2 + ((c * 8 + kt) * 32 + lane) * 16);
                mma16816(D[0][0], Abuf[0][0][kt], bf.x, bf.y);
                mma16816(D[1][0], Abuf[0][1][kt], bf.x, bf.y);
                mma16816(D[0][1], Abuf[0][0][kt], bf.z, bf.w);
                mma16816(D[1][1], Abuf[0][1][kt], bf.z, bf.w);
            }
#pragma unroll
            for (int kt = 0; kt < 4; kt++) {
                uint4 bf = *(const uint4*)(smem + WSH_O * 2 + ((c * 4 + kt) * 32 + lane) * 16);
                mma16816(D[0][0], X[0][kt], bf.x, bf.y);
                mma16816(D[1][0], X[1][kt], bf.x, bf.y);
                mma16816(D[0][1], X[0][kt], bf.z, bf.w);
                mma16816(D[1][1], X[1][kt], bf.z, bf.w);
            }
#pragma unroll
            for (int m = 0; m < 2; m++) {
                const int px_lo = base + m * 16 + gid;
                const int px_hi = px_lo + 8;
#pragma unroll
                for (int j = 0; j < 2; j++) {
                    int ch = (c * 2 + j) * 8 + tig * 2;
                    float* op = ob + (size_t)ch * HW;
                    op[px_lo]      = D[m][j][0];
                    op[HW + px_lo] = D[m][j][1];
                    op[px_hi]      = D[m][j][2];
                    op[HW + px_hi] = D[m][j][3];
                }
            }
        }
    }
}

// ============================================================
extern "C" void kernel_launch(void* const* d_in, const int* in_sizes, int n_in,
                              void* d_out, int out_size)
{
    (void)in_sizes; (void)n_in; (void)out_size;
    const float* x    = (const float*)d_in[0];
    const float* lat  = (const float*)d_in[1];
    const float* W    = (const float*)d_in[2];
    const float* bias = (const float*)d_in[3];
    float* out = (float*)d_out;

    cudaFuncSetAttribute(hyper_kernel,
                         cudaFuncAttributeMaxDynamicSharedMemorySize, 155648);
    hyper_kernel<<<148, 384, 155648>>>(lat, W, bias);

    cudaFuncSetAttribute(conv_kernel,
                         cudaFuncAttributeMaxDynamicSharedMemorySize, 110592);
    conv_kernel<<<16 * 9, 256, 110592>>>(x, out);
}

// round 17
// speedup vs baseline: 1.1869x; 1.0188x over previous
#include <cuda_runtime.h>
#include <cuda_fp16.h>
#include <cstdint>

#define FIN   64
#define FOUT  64
#define FH    128
#define LATD  512
#define NB    16
#define HW    16384
#define KTOT  53760
#define WS    53248   // fp16 elements of packed weights per sample (single-term)

// per-sample fp16 element offsets of fragment-ordered weight buffers
#define WIN_O   0        // O=128 I=64  (8192 ele)
#define WMIDA_O 8192     // O=128 I=128 (16384)
#define WMIDB_O 24576    // O=128 I=128 (16384)
#define WOUT_O  40960    // O=64 I=128  (8192)
#define WSH_O   49152    // O=64 I=64   (4096)

__device__ __align__(16) __half g_wh[NB * WS];
__device__ __align__(16) float g_bias[NB * 512];

// ---------------- helpers ----------------
__device__ __forceinline__ uint32_t pack_f16x2(float f0, float f1) {
    uint32_t r;
    asm("cvt.rn.f16x2.f32 %0, %1, %2;" : "=r"(r) : "f"(f1), "f"(f0));
    return r;
}
__device__ __forceinline__ void split2(float f0, float f1, uint32_t& hi, uint32_t& lo) {
    asm("cvt.rn.f16x2.f32 %0, %1, %2;" : "=r"(hi) : "f"(f1), "f"(f0));
    __half2 h = *(__half2*)&hi;
    float r0 = f0 - __low2float(h), r1 = f1 - __high2float(h);
    asm("cvt.rn.f16x2.f32 %0, %1, %2;" : "=r"(lo) : "f"(r1), "f"(r0));
}
__device__ __forceinline__ uint32_t smem_u32(const void* p) {
    uint32_t a;
    asm("{ .reg .u64 t; cvta.to.shared.u64 t, %1; cvt.u32.u64 %0, t; }" : "=r"(a) : "l"(p));
    return a;
}

__device__ __forceinline__ void mma16816(float d[4],
    const uint32_t a[4], uint32_t b0, uint32_t b1)
{
    asm volatile(
        "mma.sync.aligned.m16n8k16.row.col.f32.f16.f16.f32 "
        "{%0,%1,%2,%3}, {%4,%5,%6,%7}, {%8,%9}, {%0,%1,%2,%3};"
        : "+f"(d[0]), "+f"(d[1]), "+f"(d[2]), "+f"(d[3])
        : "r"(a[0]), "r"(a[1]), "r"(a[2]), "r"(a[3]), "r"(b0), "r"(b1));
}

#define CP_ASYNC16(dst, src) \
    asm volatile("cp.async.cg.shared.global [%0], [%1], 16;" :: "r"(dst), "l"(src) : "memory")
#define CP_COMMIT() asm volatile("cp.async.commit_group;" ::: "memory")
#define CP_WAIT(n)  asm volatile("cp.async.wait_group %0;" :: "n"(n) : "memory")

// map hypernet row k -> fragment element index (j-pair interleaved layout)
// fel = base + (c2*KT + kt)*256 + tl*8 + j*4 + el
__device__ __forceinline__ int map_fel(int k, float& scale, bool& isBias) {
    const float RS128 = 0.08838834764831845f;
    const float RS64  = 0.125f;
    int o, i, I, base;
    isBias = false;
    if (k < 8192)       { o = k >> 6;            i = k & 63;  I = 64;  base = WIN_O;   scale = RS128; }
    else if (k < 24576) { int x = k - 8192;  o = x >> 7; i = x & 127; I = 128; base = WMIDA_O; scale = RS128; }
    else if (k < 40960) { int x = k - 24576; o = x >> 7; i = x & 127; I = 128; base = WMIDB_O; scale = RS128; }
    else if (k < 49152) { int x = k - 40960; o = x >> 7; i = x & 127; I = 128; base = WOUT_O;  scale = RS64; }
    else if (k < 53248) { int x = k - 49152; o = x >> 6; i = x & 63;  I = 64;  base = WSH_O;   scale = RS64; }
    else { isBias = true; scale = 1.f; return 0; }
    int KT = I / 16;
    int nt = o >> 3, kt = i >> 4;
    int c2 = nt >> 1, jj = nt & 1;
    int tl = (o & 7) * 4 + ((i & 7) >> 1);
    int el = (((i >> 3) & 1) << 1) | (i & 1);
    return base + (c2 * KT + kt) * 256 + tl * 8 + jj * 4 + el;
}

// ============================================================
// Kernel A (frozen from R16): hypernetwork GEMM, tensor cores,
// cp.async-staged W, 148 CTAs x 384 thr, paired __half2 scatter.
// ============================================================
__global__ __launch_bounds__(384) void hyper_kernel(
    const float* __restrict__ lat,
    const float* __restrict__ Wm,
    const float* __restrict__ bias)
{
    extern __shared__ __align__(16) char hsm[];
    uint4* sAhi = (uint4*)hsm;               // [32][32] = 16 KB
    uint4* sAlo = (uint4*)(hsm + 16384);     // 16 KB

    const int tid  = threadIdx.x;
    const int lane = tid & 31;
    const int w    = tid >> 5;

    for (int idx = tid; idx < 1024; idx += 384) {
        int kc = idx >> 5, ln = idx & 31;
        int r = ln >> 2, c = kc * 16 + (ln & 3) * 2;
        uint32_t h[4], l[4];
        split2(lat[r * 512 + c],           lat[r * 512 + c + 1],           h[0], l[0]);
        split2(lat[(r + 8) * 512 + c],     lat[(r + 8) * 512 + c + 1],     h[1], l[1]);
        split2(lat[r * 512 + c + 8],       lat[r * 512 + c + 9],           h[2], l[2]);
        split2(lat[(r + 8) * 512 + c + 8], lat[(r + 8) * 512 + c + 9],     h[3], l[3]);
        sAhi[kc * 32 + ln] = make_uint4(h[0], h[1], h[2], h[3]);
        sAlo[kc * 32 + ln] = make_uint4(l[0], l[1], l[2], l[3]);
    }
    __syncthreads();

    const int g = blockIdx.x * 12 + w;
    if (g >= 1680) return;
    const int kbase = g * 32;
    const float* __restrict__ wrow = Wm + (size_t)kbase * 512;

    const uint32_t wbase_off = 32768 + w * 10240;
    const uint32_t wsm_hw    = smem_u32(hsm) + wbase_off;

    float acc[4][4];
#pragma unroll
    for (int t = 0; t < 4; t++) {
        acc[t][0] = 0.f; acc[t][1] = 0.f; acc[t][2] = 0.f; acc[t][3] = 0.f;
    }

    const int rrow = lane >> 2;
    const int tig  = lane & 3;

#define HSTAGE(DSTHW, KC2) do {                                              \
        const float* _s = wrow + (size_t)(lane >> 3) * 512                   \
                          + (KC2) * 32 + (lane & 7) * 4;                     \
        uint32_t _d = (DSTHW) + (lane >> 3) * 160 + (lane & 7) * 16;         \
        _Pragma("unroll")                                                    \
        for (int i = 0; i < 8; i++)                                          \
            CP_ASYNC16(_d + i * 4 * 160, _s + (size_t)i * 4 * 512);          \
    } while (0)

#define HCONS(COFF, KC) do {                                                 \
        uint4 ah4 = sAhi[(KC) * 32 + lane];                                  \
        uint4 al4 = sAlo[(KC) * 32 + lane];                                  \
        uint32_t Ah[4] = {ah4.x, ah4.y, ah4.z, ah4.w};                       \
        uint32_t Al[4] = {al4.x, al4.y, al4.z, al4.w};                       \
        const char* _c = hsm + (COFF) + ((KC) & 1) * 64 + rrow * 160 + tig * 8; \
        _Pragma("unroll")                                                    \
        for (int t = 0; t < 4; t++) {                                        \
            float2 w0 = *(const float2*)(_c + t * 8 * 160);                  \
            float2 w1 = *(const float2*)(_c + t * 8 * 160 + 32);             \
            uint32_t bh0, bl0, bh1, bl1;                                     \
            split2(w0.x, w0.y, bh0, bl0);                                    \
            split2(w1.x, w1.y, bh1, bl1);                                    \
            mma16816(acc[t], Ah, bh0, bh1);                                  \
            mma16816(acc[t], Al, bh0, bh1);                                  \
            mma16816(acc[t], Ah, bl0, bl1);                                  \
        }                                                                    \
    } while (0)

    HSTAGE(wsm_hw, 0);        CP_COMMIT();
    HSTAGE(wsm_hw + 5120, 1); CP_COMMIT();

#pragma unroll 1
    for (int kc2 = 0; kc2 < 16; kc2++) {
        CP_WAIT(1);
        __syncwarp();
        uint32_t coff = wbase_off + (kc2 & 1) * 5120;
        HCONS(coff, 2 * kc2);
        HCONS(coff, 2 * kc2 + 1);
        if (kc2 < 14)
            HSTAGE(wsm_hw + ((kc2 & 1) ? 5120u : 0u), kc2 + 2);
        CP_COMMIT();
    }
#undef HSTAGE
#undef HCONS

    const int s0 = lane >> 2;           // sample rows s0, s0+8
#pragma unroll
    for (int t = 0; t < 4; t++) {
        int k0 = kbase + t * 8 + (lane & 3) * 2;   // even k
        float bk0 = bias[k0], bk1 = bias[k0 + 1];
        float scale; bool isBias;
        int fel = map_fel(k0, scale, isBias);
        float a0 = acc[t][0] + bk0, a1 = acc[t][1] + bk1;   // sample s0
        float b0 = acc[t][2] + bk0, b1 = acc[t][3] + bk1;   // sample s0+8
        if (isBias) {
            g_bias[s0 * 512 + (k0 - 53248)]           = a0;
            g_bias[s0 * 512 + (k0 - 53248) + 1]       = a1;
            g_bias[(s0 + 8) * 512 + (k0 - 53248)]     = b0;
            g_bias[(s0 + 8) * 512 + (k0 - 53248) + 1] = b1;
        } else {
            uint32_t p0 = pack_f16x2(a0 * scale, a1 * scale);
            uint32_t p1 = pack_f16x2(b0 * scale, b1 * scale);
            *(uint32_t*)(g_wh + (size_t)s0 * WS + fel)       = p0;
            *(uint32_t*)(g_wh + (size_t)(s0 + 8) * WS + fel) = p1;
        }
    }
}

// ============================================================
// Kernel B: mma.sync fused block, fp16 single-term weights,
// M=32 per warp, j-pair-interleaved fragments (LDS.128 per (c,kt)),
// contiguous (sample,tile) work ranges over 148 CTAs:
// each CTA's 6-7 item range spans <=2 samples -> at most 1 restage.
// ============================================================
template <int KT>
__device__ __forceinline__ void layer_fused(
    const uint32_t (*A0)[4], const uint32_t (*A1)[4],
    uint32_t (*N0)[4], uint32_t (*N1)[4],
    const char* __restrict__ sm, int bOff,
    const float* __restrict__ bsm, int lane, int tig)
{
#pragma unroll
    for (int c = 0; c < 8; c++) {        // chunk = 2 nt = 16 channels
        float D[2][2][4];
#pragma unroll
        for (int j = 0; j < 2; j++) {
            int nt = c * 2 + j;
            float b0 = bsm[nt * 8 + tig * 2];
            float b1 = bsm[nt * 8 + tig * 2 + 1];
#pragma unroll
            for (int m = 0; m < 2; m++) {
                D[m][j][0] = b0; D[m][j][1] = b1;
                D[m][j][2] = b0; D[m][j][3] = b1;
            }
        }
#pragma unroll
        for (int kt = 0; kt < KT; kt++) {
            uint4 bf = *(const uint4*)(sm + bOff + ((c * KT + kt) * 32 + lane) * 16);
            mma16816(D[0][0], A0[kt], bf.x, bf.y);
            mma16816(D[1][0], A1[kt], bf.x, bf.y);
            mma16816(D[0][1], A0[kt], bf.z, bf.w);
            mma16816(D[1][1], A1[kt], bf.z, bf.w);
        }
#pragma unroll
        for (int m = 0; m < 2; m++) {
            uint32_t (*N)[4] = m ? N1 : N0;
            N[c][0] = pack_f16x2(fmaxf(D[m][0][0], 0.f), fmaxf(D[m][0][1], 0.f));
            N[c][1] = pack_f16x2(fmaxf(D[m][0][2], 0.f), fmaxf(D[m][0][3], 0.f));
            N[c][2] = pack_f16x2(fmaxf(D[m][1][0], 0.f), fmaxf(D[m][1][1], 0.f));
            N[c][3] = pack_f16x2(fmaxf(D[m][1][2], 0.f), fmaxf(D[m][1][3], 0.f));
        }
    }
}

__global__ __launch_bounds__(256, 1) void conv_kernel(
    const float* __restrict__ x, float* __restrict__ out)
{
    extern __shared__ __align__(16) char smem[];
    const float* bsm = (const float*)(smem + WS * 2);

    const int tid = threadIdx.x;
    const int w = tid >> 5, lane = tid & 31;
    const int gid = lane >> 2, tig = lane & 3;

    const int start = (blockIdx.x * 1024) / 148;
    const int end   = ((blockIdx.x + 1) * 1024) / 148;

    uint32_t X[2][4][4];
    uint32_t Abuf[2][2][8][4];   // ping-pong [pp][half][kt][4]

    int bcur = -1;

    for (int item = start; item < end; item++) {
        const int b = item >> 6;
        const int t = item & 63;

        if (b != bcur) {
            __syncthreads();
            const uint4* src = (const uint4*)(g_wh + (size_t)b * WS);
            uint4* dst = (uint4*)smem;
            for (int i = tid; i < WS / 8; i += 256) dst[i] = src[i];
            const float4* bsrc = (const float4*)(g_bias + b * 512);
            float4* bdst = (float4*)(smem + WS * 2);
            if (tid < 128) bdst[tid] = bsrc[tid];
            __syncthreads();
            bcur = b;
        }

        const float* xb = x + (size_t)b * FIN * HW;
        float* ob = out + (size_t)b * FOUT * HW;
        const int base = t * 256 + w * 32;

        // ---- load x as fp16 A fragments for both m16 halves ----
#pragma unroll
        for (int m = 0; m < 2; m++) {
            const int px_lo = base + m * 16 + gid;
            const int px_hi = px_lo + 8;
#pragma unroll
            for (int kt = 0; kt < 4; kt++) {
                const float* xp = xb + (size_t)(kt * 16 + tig * 2) * HW;
                X[m][kt][0] = pack_f16x2(xp[px_lo],          xp[HW + px_lo]);
                X[m][kt][1] = pack_f16x2(xp[px_hi],          xp[HW + px_hi]);
                X[m][kt][2] = pack_f16x2(xp[8 * HW + px_lo], xp[9 * HW + px_lo]);
                X[m][kt][3] = pack_f16x2(xp[8 * HW + px_hi], xp[9 * HW + px_hi]);
            }
        }

        layer_fused<4>(X[0], X[1], Abuf[0][0], Abuf[0][1],
                       smem, WIN_O * 2, bsm + 0, lane, tig);
        layer_fused<8>(Abuf[0][0], Abuf[0][1], Abuf[1][0], Abuf[1][1],
                       smem, WMIDA_O * 2, bsm + 128, lane, tig);
        layer_fused<8>(Abuf[1][0], Abuf[1][1], Abuf[0][0], Abuf[0][1],
                       smem, WMIDB_O * 2, bsm + 256, lane, tig);

        // ---- out layer: Wout @ h + Wshort @ x ----
#pragma unroll
        for (int c = 0; c < 4; c++) {
            float D[2][2][4];
#pragma unroll
            for (int j = 0; j < 2; j++) {
                int ch = (c * 2 + j) * 8 + tig * 2;
                float b0 = bsm[384 + ch]     + bsm[448 + ch];
                float b1 = bsm[384 + ch + 1] + bsm[448 + ch + 1];
#pragma unroll
                for (int m = 0; m < 2; m++) {
                    D[m][j][0] = b0; D[m][j][1] = b1;
                    D[m][j][2] = b0; D[m][j][3] = b1;
                }
            }
#pragma unroll
            for (int kt = 0; kt < 8; kt++) {
                uint4 bf = *(const uint4*)(smem + WOUT_O * 2 + ((c * 8 + kt) * 32 + lane) * 16);
                mma16816(D[0][0], Abuf[0][0][kt], bf.x, bf.y);
                mma16816(D[1][0], Abuf[0][1][kt], bf.x, bf.y);
                mma16816(D[0][1], Abuf[0][0][kt], bf.z, bf.w);
                mma16816(D[1][1], Abuf[0][1][kt], bf.z, bf.w);
            }
#pragma unroll
            for (int kt = 0; kt < 4; kt++) {
                uint4 bf = *(const uint4*)(smem + WSH_O * 2 + ((c * 4 + kt) * 32 + lane) * 16);
                mma16816(D[0][0], X[0][kt], bf.x, bf.y);
                mma16816(D[1][0], X[1][kt], bf.x, bf.y);
                mma16816(D[0][1], X[0][kt], bf.z, bf.w);
                mma16816(D[1][1], X[1][kt], bf.z, bf.w);
            }
#pragma unroll
            for (int m = 0; m < 2; m++) {
                const int px_lo = base + m * 16 + gid;
                const int px_hi = px_lo + 8;
#pragma unroll
                for (int j = 0; j < 2; j++) {
                    int ch = (c * 2 + j) * 8 + tig * 2;
                    float* op = ob + (size_t)ch * HW;
                    op[px_lo]      = D[m][j][0];
                    op[HW + px_lo] = D[m][j][1];
                    op[px_hi]      = D[m][j][2];
                    op[HW + px_hi] = D[m][j][3];
                }
            }
        }
    }
}

// ============================================================
extern "C" void kernel_launch(void* const* d_in, const int* in_sizes, int n_in,
                              void* d_out, int out_size)
{
    (void)in_sizes; (void)n_in; (void)out_size;
    const float* x    = (const float*)d_in[0];
    const float* lat  = (const float*)d_in[1];
    const float* W    = (const float*)d_in[2];
    const float* bias = (const float*)d_in[3];
    float* out = (float*)d_out;

    cudaFuncSetAttribute(hyper_kernel,
                         cudaFuncAttributeMaxDynamicSharedMemorySize, 155648);
    hyper_kernel<<<148, 384, 155648>>>(lat, W, bias);

    cudaFuncSetAttribute(conv_kernel,
                         cudaFuncAttributeMaxDynamicSharedMemorySize, 110592);
    conv_kernel<<<148, 256, 110592>>>(x, out);
}